// round 1
// baseline (speedup 1.0000x reference)
#include <cuda_runtime.h>
#include <stdint.h>

#define BB      8
#define NN      197
#define DIM     64
#define HEADS   2
#define DH      32
#define INNER   64
#define NSPLIT  3
#define CH      66      // ceil(197/3)
#define SCALE   0.17677669529663687f   // 32^-0.5

// ---------------- scratch (no allocations allowed) ----------------
__device__ float g_xn[BB * NN * DIM];
__device__ float g_q [BB * HEADS * NN * DH];
__device__ float g_k [BB * HEADS * NN * DH];
__device__ float g_attn[NN * BB * HEADS * NN];          // [n][b][h][m]
__device__ float g_part[NSPLIT * NN * BB * INNER];      // [sp][n][b][e]

// ---------------- cp.async helpers ----------------
__device__ __forceinline__ void cp16(void* dst, const void* src) {
    uint32_t d = (uint32_t)__cvta_generic_to_shared(dst);
    asm volatile("cp.async.cg.shared.global [%0], [%1], 16;\n" :: "r"(d), "l"(src) : "memory");
}
__device__ __forceinline__ void cp8(void* dst, const void* src) {
    uint32_t d = (uint32_t)__cvta_generic_to_shared(dst);
    asm volatile("cp.async.ca.shared.global [%0], [%1], 8;\n" :: "r"(d), "l"(src) : "memory");
}
__device__ __forceinline__ void cp_commit() {
    asm volatile("cp.async.commit_group;\n" ::: "memory");
}
__device__ __forceinline__ void cp_wait0() {
    asm volatile("cp.async.wait_group 0;\n" ::: "memory");
}

// ---------------- K1: LayerNorm + QK projection ----------------
__global__ __launch_bounds__(128) void k_ln_qk(
    const float* __restrict__ x, const float* __restrict__ gamma,
    const float* __restrict__ beta, const float* __restrict__ wqk)
{
    int row = blockIdx.x;              // b*NN + n
    int t = threadIdx.x;               // 128
    __shared__ float sx[DIM], sxn[DIM], sred[2];
    if (t < DIM) sx[t] = x[row * DIM + t];
    __syncthreads();
    if (t < 32) {
        float v  = sx[t] + sx[t + 32];
        float v2 = sx[t] * sx[t] + sx[t + 32] * sx[t + 32];
        #pragma unroll
        for (int o = 16; o; o >>= 1) {
            v  += __shfl_down_sync(0xffffffffu, v,  o);
            v2 += __shfl_down_sync(0xffffffffu, v2, o);
        }
        if (t == 0) {
            float mu  = v  * (1.0f / DIM);
            float var = v2 * (1.0f / DIM) - mu * mu;
            sred[0] = mu;
            sred[1] = rsqrtf(var + 1e-5f);
        }
    }
    __syncthreads();
    if (t < DIM) {
        float xn = (sx[t] - sred[0]) * sred[1] * gamma[t] + beta[t];
        sxn[t] = xn;
        g_xn[row * DIM + t] = xn;
    }
    __syncthreads();
    float acc = 0.0f;
    #pragma unroll 16
    for (int d = 0; d < DIM; d++) acc += sxn[d] * wqk[d * 128 + t];
    int b = row / NN, n = row % NN;
    int h = (t & 63) >> 5, dh = t & 31;
    int off = ((b * HEADS + h) * NN + n) * DH + dh;
    if (t < 64) g_q[off] = acc; else g_k[off] = acc;
}

// ---------------- K2: dots + softmax ----------------
__global__ __launch_bounds__(256) void k_attn(void)
{
    int bhn = blockIdx.x;              // (b*HEADS+h)*NN + n
    int n  = bhn % NN;
    int bh = bhn / NN;                 // b*HEADS+h
    int b  = bh / HEADS;
    int h  = bh % HEADS;
    int t  = threadIdx.x;              // 256
    __shared__ float sq[DH];
    __shared__ float ssc[256];
    if (t < DH) sq[t] = g_q[(bh * NN + n) * DH + t];
    __syncthreads();
    float sc = -1e30f;
    if (t < NN) {
        const float* kr = &g_k[(bh * NN + t) * DH];
        float a = 0.0f;
        #pragma unroll
        for (int d = 0; d < DH; d++) a += sq[d] * kr[d];
        sc = a * SCALE;
    }
    ssc[t] = sc;
    __syncthreads();
    #pragma unroll
    for (int o = 128; o >= 1; o >>= 1) {
        if (t < o) ssc[t] = fmaxf(ssc[t], ssc[t + o]);
        __syncthreads();
    }
    float mx = ssc[0];
    __syncthreads();
    float e = (t < NN) ? __expf(sc - mx) : 0.0f;
    ssc[t] = e;
    __syncthreads();
    #pragma unroll
    for (int o = 128; o >= 1; o >>= 1) {
        if (t < o) ssc[t] += ssc[t + o];
        __syncthreads();
    }
    float inv = 1.0f / ssc[0];
    if (t < NN)
        g_attn[((n * BB + b) * HEADS + h) * NN + t] = e * inv;
}

// ---------------- K3: heavy gathered per-pair projection + attn contraction ----------------
__global__ __launch_bounds__(256) void k_heavy(
    const float* __restrict__ up, const int* __restrict__ imap)
{
    int n  = blockIdx.x;
    int sp = blockIdx.y;
    int m0 = sp * CH;
    int cnt = NN - m0; if (cnt > CH) cnt = CH;
    int t = threadIdx.x;               // 256

    int dq = t >> 6;                   // d-quarter 0..3
    int s  = t & 63;
    int b2 = s >> 4;                   // b-pair 0..3
    int eq = s & 15;                   // e-quad 0..15
    int b_0 = b2 * 2, b_1 = b_0 + 1;
    int e0 = eq * 4;
    int h  = eq >> 3;
    int d0 = dq * 16;

    __shared__ __align__(16) float Wbuf[2][DIM * INNER];
    __shared__ __align__(16) float xbuf[2][BB * DIM];
    __shared__ float s_attn[BB * HEADS][CH];
    __shared__ int   s_idx[CH];

    for (int i = t; i < cnt; i += 256) s_idx[i] = imap[n * NN + m0 + i];
    for (int i = t; i < BB * HEADS * cnt; i += 256) {
        int bh = i / cnt, mm = i - bh * cnt;
        s_attn[bh][mm] = g_attn[(n * BB * HEADS + bh) * NN + m0 + mm];
    }
    __syncthreads();

    int bb = t >> 5, dd2 = (t & 31) * 2;
    // prefetch buffer 0
    {
        const float* src = up + (size_t)s_idx[0] * 4096;
        #pragma unroll
        for (int k = 0; k < 4; k++)
            cp16(&Wbuf[0][(t + 256 * k) * 4], src + (t + 256 * k) * 4);
        cp8(&xbuf[0][bb * 64 + dd2], &g_xn[(bb * NN + m0) * DIM + dd2]);
        cp_commit();
        cp_wait0();
    }
    __syncthreads();

    float acc[2][4];
    #pragma unroll
    for (int j = 0; j < 4; j++) { acc[0][j] = 0.0f; acc[1][j] = 0.0f; }

    for (int i = 0; i < cnt; i++) {
        int cur = i & 1, nxt = cur ^ 1;
        if (i + 1 < cnt) {
            const float* src = up + (size_t)s_idx[i + 1] * 4096;
            #pragma unroll
            for (int k = 0; k < 4; k++)
                cp16(&Wbuf[nxt][(t + 256 * k) * 4], src + (t + 256 * k) * 4);
            cp8(&xbuf[nxt][bb * 64 + dd2], &g_xn[(bb * NN + m0 + i + 1) * DIM + dd2]);
            cp_commit();
        }
        const float* Wc = Wbuf[cur];
        const float* xc = xbuf[cur];

        float4 y0 = make_float4(0.f, 0.f, 0.f, 0.f);
        float4 y1 = make_float4(0.f, 0.f, 0.f, 0.f);
        #pragma unroll
        for (int dd = 0; dd < 16; dd += 4) {
            float4 xa = *(const float4*)&xc[b_0 * 64 + d0 + dd];
            float4 xb = *(const float4*)&xc[b_1 * 64 + d0 + dd];
            #pragma unroll
            for (int r = 0; r < 4; r++) {
                float4 w = *(const float4*)&Wc[(d0 + dd + r) * 64 + e0];
                float xav = (r == 0) ? xa.x : (r == 1) ? xa.y : (r == 2) ? xa.z : xa.w;
                float xbv = (r == 0) ? xb.x : (r == 1) ? xb.y : (r == 2) ? xb.z : xb.w;
                y0.x += xav * w.x; y0.y += xav * w.y; y0.z += xav * w.z; y0.w += xav * w.w;
                y1.x += xbv * w.x; y1.y += xbv * w.y; y1.z += xbv * w.z; y1.w += xbv * w.w;
            }
        }
        float a0 = s_attn[b_0 * HEADS + h][i];
        float a1 = s_attn[b_1 * HEADS + h][i];
        acc[0][0] += a0 * y0.x; acc[0][1] += a0 * y0.y; acc[0][2] += a0 * y0.z; acc[0][3] += a0 * y0.w;
        acc[1][0] += a1 * y1.x; acc[1][1] += a1 * y1.y; acc[1][2] += a1 * y1.z; acc[1][3] += a1 * y1.w;

        cp_wait0();
        __syncthreads();
    }

    // reduce the 4 d-quarters, write partials
    float* red = Wbuf[0];              // reuse: 256*8 floats = 8 KB
    #pragma unroll
    for (int j = 0; j < 8; j++) red[t * 8 + j] = acc[j >> 2][j & 3];
    __syncthreads();
    if (t < 64) {
        #pragma unroll
        for (int j = 0; j < 8; j++) {
            float v = red[t * 8 + j] + red[(t + 64) * 8 + j]
                    + red[(t + 128) * 8 + j] + red[(t + 192) * 8 + j];
            int bbo = (t >> 4) * 2 + (j >> 2);
            int ee  = (t & 15) * 4 + (j & 3);
            g_part[((sp * NN + n) * BB + bbo) * INNER + ee] = v;
        }
    }
}

// ---------------- K4: reduce splits + output projection ----------------
__global__ __launch_bounds__(64) void k_out(
    const float* __restrict__ wout, const float* __restrict__ bout,
    float* __restrict__ out)
{
    int row = blockIdx.x;              // b*NN + n
    int b = row / NN, n = row % NN;
    int t = threadIdx.x;               // 64
    __shared__ float sv[INNER];
    float v = 0.0f;
    #pragma unroll
    for (int sp = 0; sp < NSPLIT; sp++)
        v += g_part[((sp * NN + n) * BB + b) * INNER + t];
    sv[t] = v;
    __syncthreads();
    float acc = bout[t];
    #pragma unroll 16
    for (int e = 0; e < INNER; e++) acc += sv[e] * wout[e * DIM + t];
    out[row * DIM + t] = acc;
}

// ---------------- launch ----------------
extern "C" void kernel_launch(void* const* d_in, const int* in_sizes, int n_in,
                              void* d_out, int out_size)
{
    (void)in_sizes; (void)n_in; (void)out_size;
    const float* x     = (const float*)d_in[0];
    const float* gamma = (const float*)d_in[1];
    const float* beta  = (const float*)d_in[2];
    const float* wqk   = (const float*)d_in[3];
    const float* up    = (const float*)d_in[4];
    const float* wout  = (const float*)d_in[5];
    const float* bout  = (const float*)d_in[6];
    const int*   imap  = (const int*)d_in[7];
    float* out = (float*)d_out;

    k_ln_qk<<<BB * NN, 128>>>(x, gamma, beta, wqk);
    k_attn<<<BB * HEADS * NN, 256>>>();
    dim3 g3(NN, NSPLIT);
    k_heavy<<<g3, 256>>>(up, imap);
    k_out<<<BB * NN, 64>>>(wout, bout, out);
}

// round 11
// speedup vs baseline: 1.0627x; 1.0627x over previous
#include <cuda_runtime.h>
#include <stdint.h>

#define BB      8
#define NN      197
#define DIM     64
#define HEADS   2
#define DH      32
#define INNER   64
#define NSPLIT  3
#define CH      66
#define SCALE   0.17677669529663687f

// ---------------- scratch ----------------
__device__ float g_xn[BB * NN * DIM];
__device__ float g_q [BB * HEADS * NN * DH];
__device__ float g_k [BB * HEADS * NN * DH];
__device__ float g_attn[NN * BB * HEADS * NN];          // [n][b][h][m]
__device__ float g_part[NSPLIT * NN * BB * INNER];      // [sp][n][b][e]

// ---------------- f32x2 + cp.async helpers ----------------
__device__ __forceinline__ uint64_t dup2(float v) {
    uint64_t r; asm("mov.b64 %0, {%1, %1};" : "=l"(r) : "f"(v)); return r;
}
__device__ __forceinline__ uint64_t pk2(float a, float b) {
    uint64_t r; asm("mov.b64 %0, {%1, %2};" : "=l"(r) : "f"(a), "f"(b)); return r;
}
__device__ __forceinline__ void fma2(uint64_t& d, uint64_t a, uint64_t b) {
    asm("fma.rn.f32x2 %0, %1, %2, %0;" : "+l"(d) : "l"(a), "l"(b));
}
__device__ __forceinline__ void unpk2(float& lo, float& hi, uint64_t v) {
    asm("mov.b64 {%0, %1}, %2;" : "=f"(lo), "=f"(hi) : "l"(v));
}
__device__ __forceinline__ void cp16(void* dst, const void* src) {
    uint32_t d = (uint32_t)__cvta_generic_to_shared(dst);
    asm volatile("cp.async.cg.shared.global [%0], [%1], 16;\n" :: "r"(d), "l"(src) : "memory");
}
__device__ __forceinline__ void cp_commit() {
    asm volatile("cp.async.commit_group;\n" ::: "memory");
}
__device__ __forceinline__ void cp_wait0() {
    asm volatile("cp.async.wait_group 0;\n" ::: "memory");
}

// ---------------- K1: LayerNorm + QK projection ----------------
__global__ __launch_bounds__(128) void k_ln_qk(
    const float* __restrict__ x, const float* __restrict__ gamma,
    const float* __restrict__ beta, const float* __restrict__ wqk)
{
    int row = blockIdx.x;
    int t = threadIdx.x;
    __shared__ float sx[DIM], sxn[DIM], sred[2];
    if (t < DIM) sx[t] = x[row * DIM + t];
    __syncthreads();
    if (t < 32) {
        float v  = sx[t] + sx[t + 32];
        float v2 = sx[t] * sx[t] + sx[t + 32] * sx[t + 32];
        #pragma unroll
        for (int o = 16; o; o >>= 1) {
            v  += __shfl_down_sync(0xffffffffu, v,  o);
            v2 += __shfl_down_sync(0xffffffffu, v2, o);
        }
        if (t == 0) {
            float mu  = v  * (1.0f / DIM);
            float var = v2 * (1.0f / DIM) - mu * mu;
            sred[0] = mu;
            sred[1] = rsqrtf(var + 1e-5f);
        }
    }
    __syncthreads();
    if (t < DIM) {
        float xn = (sx[t] - sred[0]) * sred[1] * gamma[t] + beta[t];
        sxn[t] = xn;
        g_xn[row * DIM + t] = xn;
    }
    __syncthreads();
    float acc = 0.0f;
    #pragma unroll 16
    for (int d = 0; d < DIM; d++) acc += sxn[d] * wqk[d * 128 + t];
    int b = row / NN, n = row % NN;
    int h = (t & 63) >> 5, dh = t & 31;
    int off = ((b * HEADS + h) * NN + n) * DH + dh;
    if (t < 64) g_q[off] = acc; else g_k[off] = acc;
}

// ---------------- K2: dots + softmax (warp-shuffle reductions) ----------------
__global__ __launch_bounds__(224) void k_attn(void)
{
    int bhn = blockIdx.x;              // (b*HEADS+h)*NN + n
    int n  = bhn % NN;
    int bh = bhn / NN;
    int b  = bh / HEADS;
    int h  = bh % HEADS;
    int t  = threadIdx.x;              // 224
    int wid = t >> 5, lid = t & 31;
    __shared__ float sq[DH];
    __shared__ float wred[7];
    __shared__ float sb[2];
    if (t < DH) sq[t] = g_q[(bh * NN + n) * DH + t];
    __syncthreads();
    float sc = -1e30f;
    if (t < NN) {
        const float* kr = &g_k[(bh * NN + t) * DH];
        float a = 0.0f;
        #pragma unroll
        for (int d = 0; d < DH; d++) a += sq[d] * kr[d];
        sc = a * SCALE;
    }
    float m = sc;
    #pragma unroll
    for (int o = 16; o; o >>= 1) m = fmaxf(m, __shfl_xor_sync(0xffffffffu, m, o));
    if (lid == 0) wred[wid] = m;
    __syncthreads();
    if (t == 0) {
        float mm = wred[0];
        #pragma unroll
        for (int w = 1; w < 7; w++) mm = fmaxf(mm, wred[w]);
        sb[0] = mm;
    }
    __syncthreads();
    float e = (t < NN) ? __expf(sc - sb[0]) : 0.0f;
    float s = e;
    #pragma unroll
    for (int o = 16; o; o >>= 1) s += __shfl_xor_sync(0xffffffffu, s, o);
    if (lid == 0) wred[wid] = s;
    __syncthreads();
    if (t == 0) {
        float ss = 0.0f;
        #pragma unroll
        for (int w = 0; w < 7; w++) ss += wred[w];
        sb[1] = 1.0f / ss;
    }
    __syncthreads();
    if (t < NN)
        g_attn[((n * BB + b) * HEADS + h) * NN + t] = e * sb[1];
}

// ---------------- K3: heavy kernel, f32x2 packed ----------------
// smem pool layout (float words):
#define OFF_W    0        // 2 x 4096  (double-buffered W tile)
#define OFF_XR   8192     // 2 x 512   (raw xn rows)
#define OFF_XH   9216     // 2 x 1088  (attn-folded x, [b][h] rows stride 68)
#define OFF_ATT  11392    // 16 x 66
#define POOL_F   12448

__global__ __launch_bounds__(128, 3) void k_heavy(
    const float* __restrict__ up, const int* __restrict__ imap)
{
    int n  = blockIdx.x;
    int sp = blockIdx.y;
    int m0 = sp * CH;
    int cnt = NN - m0; if (cnt > CH) cnt = CH;
    int t = threadIdx.x;               // 128

    int dgrp = t >> 3;                 // 0..15
    int egrp = t & 7;                  // 0..7

    __shared__ __align__(16) float pool[POOL_F];
    __shared__ int s_idx[CH];

    // stage index row + attn rows
    for (int i = t; i < cnt; i += 128) s_idx[i] = imap[n * NN + m0 + i];
    for (int i = t; i < BB * HEADS * cnt; i += 128) {
        int bh = i / cnt, mm = i - bh * cnt;
        pool[OFF_ATT + bh * CH + mm] =
            g_attn[(n * BB * HEADS + bh) * NN + m0 + mm];
    }
    __syncthreads();

    int xb = t >> 4, xd = (t & 15) * 4;    // for x staging: b, d-offset

    // prefetch iter 0 into buffer 0
    {
        const float* src = up + (size_t)s_idx[0] * 4096;
        #pragma unroll
        for (int k = 0; k < 8; k++)
            cp16(&pool[OFF_W + (t + 128 * k) * 4], src + (t + 128 * k) * 4);
        cp16(&pool[OFF_XR + t * 4], &g_xn[(xb * NN + m0) * DIM + xd]);
        cp_commit();
        cp_wait0();
    }
    __syncthreads();

    // transform buffer 0: xh[b][h][d] = attn[b,h,m0] * xn[b,m0,d]
    {
        int bh = t >> 3;                    // 0..15
        int dblk = (t & 7) * 8;             // 0..56
        float a = pool[OFF_ATT + bh * CH + 0];
        const float* xr = &pool[OFF_XR + (bh >> 1) * 64 + dblk];
        float4 v0 = *(const float4*)&xr[0];
        float4 v1 = *(const float4*)&xr[4];
        float* xdst = &pool[OFF_XH + bh * 68 + dblk];
        *(float4*)&xdst[0] = make_float4(a*v0.x, a*v0.y, a*v0.z, a*v0.w);
        *(float4*)&xdst[4] = make_float4(a*v1.x, a*v1.y, a*v1.z, a*v1.w);
    }
    __syncthreads();

    uint64_t acc[8][4];
    #pragma unroll
    for (int b = 0; b < 8; b++)
        #pragma unroll
        for (int j = 0; j < 4; j++) acc[b][j] = 0ull;

    for (int i = 0; i < cnt; i++) {
        int p = i & 1;
        if (i + 1 < cnt) {
            int np = p ^ 1;
            const float* src = up + (size_t)s_idx[i + 1] * 4096;
            #pragma unroll
            for (int k = 0; k < 8; k++)
                cp16(&pool[OFF_W + np * 4096 + (t + 128 * k) * 4],
                     src + (t + 128 * k) * 4);
            cp16(&pool[OFF_XR + np * 512 + t * 4],
                 &g_xn[(xb * NN + m0 + i + 1) * DIM + xd]);
            cp_commit();
        }

        // ---- compute on buffer p ----
        const float* Wc = &pool[OFF_W + p * 4096];
        const float* xh = &pool[OFF_XH + p * 1088];
        #pragma unroll
        for (int h = 0; h < 2; h++) {
            float4 xq[8];
            #pragma unroll
            for (int b = 0; b < 8; b++)
                xq[b] = *(const float4*)&xh[(b * 2 + h) * 68 + dgrp * 4];
            int q = h * 32 + egrp * 4;
            #pragma unroll
            for (int dd = 0; dd < 4; dd++) {
                float4 w = *(const float4*)&Wc[(dgrp * 4 + dd) * 64 + q];
                uint64_t w01 = pk2(w.x, w.y);
                uint64_t w23 = pk2(w.z, w.w);
                #pragma unroll
                for (int b = 0; b < 8; b++) {
                    float xv = (dd == 0) ? xq[b].x : (dd == 1) ? xq[b].y
                             : (dd == 2) ? xq[b].z : xq[b].w;
                    uint64_t x2 = dup2(xv);
                    fma2(acc[b][h * 2 + 0], x2, w01);
                    fma2(acc[b][h * 2 + 1], x2, w23);
                }
            }
        }

        if (i + 1 < cnt) {
            cp_wait0();
            __syncthreads();
            // transform buffer np for iter i+1
            int np = p ^ 1;
            int bh = t >> 3;
            int dblk = (t & 7) * 8;
            float a = pool[OFF_ATT + bh * CH + (i + 1)];
            const float* xr = &pool[OFF_XR + np * 512 + (bh >> 1) * 64 + dblk];
            float4 v0 = *(const float4*)&xr[0];
            float4 v1 = *(const float4*)&xr[4];
            float* xdst = &pool[OFF_XH + np * 1088 + bh * 68 + dblk];
            *(float4*)&xdst[0] = make_float4(a*v0.x, a*v0.y, a*v0.z, a*v0.w);
            *(float4*)&xdst[4] = make_float4(a*v1.x, a*v1.y, a*v1.z, a*v1.w);
            __syncthreads();
        }
    }
    __syncthreads();   // all compute done; overlay reduce scratch on pool

    // ---- cross-dgrp reduce (16-way) ----
    // red word addr: dgrp*530 + egrp*66 + (b*4+j)*2
    #pragma unroll
    for (int b = 0; b < 8; b++)
        #pragma unroll
        for (int j = 0; j < 4; j++) {
            float lo, hi; unpk2(lo, hi, acc[b][j]);
            *(float2*)&pool[dgrp * 530 + egrp * 66 + (b * 4 + j) * 2] =
                make_float2(lo, hi);
        }
    __syncthreads();
    #pragma unroll
    for (int r = 0; r < 2; r++) {
        int idx = t * 2 + r;               // 0..255
        int eg  = idx >> 5;
        int rem = idx & 31;                // b*4 + j
        int b   = rem >> 2;
        int j   = rem & 3;
        float2 s = make_float2(0.f, 0.f);
        #pragma unroll
        for (int dg = 0; dg < 16; dg++) {
            float2 v = *(const float2*)&pool[dg * 530 + eg * 66 + rem * 2];
            s.x += v.x; s.y += v.y;
        }
        int e0 = (j < 2) ? (eg * 4 + j * 2) : (32 + eg * 4 + (j - 2) * 2);
        *(float2*)&g_part[((sp * NN + n) * BB + b) * INNER + e0] = s;
    }
}

// ---------------- K4: reduce splits + output projection ----------------
__global__ __launch_bounds__(256) void k_out(
    const float* __restrict__ wout, const float* __restrict__ bout,
    float* __restrict__ out)
{
    int t = threadIdx.x;
    int g = t >> 6;                       // 0..3
    int t64 = t & 63;
    int row = blockIdx.x * 4 + g;         // 1576 rows = 394*4 exactly
    int b = row / NN, n = row % NN;
    __shared__ float sv[4][INNER];
    float v = 0.0f;
    #pragma unroll
    for (int sp = 0; sp < NSPLIT; sp++)
        v += g_part[((sp * NN + n) * BB + b) * INNER + t64];
    sv[g][t64] = v;
    __syncthreads();
    float acc = bout[t64];
    #pragma unroll 16
    for (int e = 0; e < INNER; e++) acc += sv[g][e] * wout[e * DIM + t64];
    out[row * DIM + t64] = acc;
}

// ---------------- launch ----------------
extern "C" void kernel_launch(void* const* d_in, const int* in_sizes, int n_in,
                              void* d_out, int out_size)
{
    (void)in_sizes; (void)n_in; (void)out_size;
    const float* x     = (const float*)d_in[0];
    const float* gamma = (const float*)d_in[1];
    const float* beta  = (const float*)d_in[2];
    const float* wqk   = (const float*)d_in[3];
    const float* up    = (const float*)d_in[4];
    const float* wout  = (const float*)d_in[5];
    const float* bout  = (const float*)d_in[6];
    const int*   imap  = (const int*)d_in[7];
    float* out = (float*)d_out;

    k_ln_qk<<<BB * NN, 128>>>(x, gamma, beta, wqk);
    k_attn<<<BB * HEADS * NN, 224>>>();
    dim3 g3(NN, NSPLIT);
    k_heavy<<<g3, 128>>>(up, imap);
    k_out<<<(BB * NN) / 4, 256>>>(wout, bout, out);
}